// round 3
// baseline (speedup 1.0000x reference)
#include <cuda_runtime.h>
#include <cuda_bf16.h>
#include <math.h>

// CausalSelfAttention: B=4, N=1024, D=1024, H=16, DH=64
//   y = einsum('bnd,hde->bhne', x, Wkqv) + bkqv   (e = 2112 = K|Q|V)
//   A = softmax_causal(q k^T / sqrt(D))           (q,k are FULL D per head)
//   sa = einsum('bhnm,bhmd->bnhd', A, v)          (v is DH=64 per head)
//   out = sa @ Wp + bp
//
// Round-3: fused flash-style attention (logits+softmax+AV in one kernel),
// scratch reduced 800 MB -> 544 MB (g_A eliminated).

#define Bc 4
#define Nc 1024
#define Dc 1024
#define Hc 16
#define DHc 64
#define Ec (2 * Dc + DHc)   // 2112
#define Mc (Bc * Nc)        // 4096

// ---- scratch (device globals: allocation-free rule) ----
__device__ float g_Q[(size_t)Bc * Hc * Nc * Dc];   // 256 MB, [bh, n, d]
__device__ float g_K[(size_t)Bc * Hc * Nc * Dc];   // 256 MB
__device__ float g_V[(size_t)Bc * Hc * Nc * DHc];  // 16 MB
__device__ float g_SA[(size_t)Bc * Nc * Dc];       // 16 MB, [b, n, h*DH+dh]

// ============================================================
// GEMM1: QKV projection. Per head: X(4096x1024) @ Wkqv[h](1024x2112) + bias.
// ============================================================
__global__ __launch_bounds__(256) void k_qkv(const float* __restrict__ x,
                                             const float* __restrict__ W,
                                             const float* __restrict__ bias) {
    const int h  = blockIdx.z;
    const int m0 = blockIdx.x * 128;
    const int e0 = blockIdx.y * 128;
    const float* __restrict__ Wh = W + (size_t)h * Dc * Ec;

    __shared__ float As[8][128];
    __shared__ float Bs[8][128];

    const int tid = threadIdx.x;
    const int tm = (tid >> 4) << 3;
    const int tn = (tid & 15) << 3;
    const int ar = tid >> 1, ac = (tid & 1) << 2;
    const int br = tid >> 5, bc = (tid & 31) << 2;
    const bool bvalid = (e0 + bc) < Ec;

    float acc[8][8];
#pragma unroll
    for (int i = 0; i < 8; i++)
#pragma unroll
        for (int j = 0; j < 8; j++) acc[i][j] = 0.f;

    for (int k0 = 0; k0 < Dc; k0 += 8) {
        float4 av = *(const float4*)(x + (size_t)(m0 + ar) * Dc + k0 + ac);
        float4 bv = make_float4(0.f, 0.f, 0.f, 0.f);
        if (bvalid) bv = *(const float4*)(Wh + (size_t)(k0 + br) * Ec + e0 + bc);
        __syncthreads();
        As[ac + 0][ar] = av.x; As[ac + 1][ar] = av.y;
        As[ac + 2][ar] = av.z; As[ac + 3][ar] = av.w;
        Bs[br][bc + 0] = bv.x; Bs[br][bc + 1] = bv.y;
        Bs[br][bc + 2] = bv.z; Bs[br][bc + 3] = bv.w;
        __syncthreads();
#pragma unroll
        for (int k = 0; k < 8; k++) {
            float a[8], b[8];
            *(float4*)&a[0] = *(const float4*)&As[k][tm];
            *(float4*)&a[4] = *(const float4*)&As[k][tm + 4];
            *(float4*)&b[0] = *(const float4*)&Bs[k][tn];
            *(float4*)&b[4] = *(const float4*)&Bs[k][tn + 4];
#pragma unroll
            for (int i = 0; i < 8; i++)
#pragma unroll
                for (int j = 0; j < 8; j++) acc[i][j] += a[i] * b[j];
        }
    }

    float bv8[8];
#pragma unroll
    for (int j = 0; j < 8; j++) {
        const int e = e0 + tn + j;
        bv8[j] = (e < Ec) ? bias[h * Ec + e] : 0.f;
    }

#pragma unroll
    for (int i = 0; i < 8; i++) {
        const int mm = m0 + tm + i;
        const int b_ = mm >> 10;
        const int n  = mm & (Nc - 1);
        const size_t base = (size_t)(b_ * Hc + h) * Nc + n;
#pragma unroll
        for (int j = 0; j < 8; j++) {
            const int e = e0 + tn + j;
            if (e < Ec) {
                const float v = acc[i][j] + bv8[j];
                if (e < Dc)            g_K[base * Dc + e] = v;
                else if (e < 2 * Dc)   g_Q[base * Dc + (e - Dc)] = v;
                else                   g_V[base * DHc + (e - 2 * Dc)] = v;
            }
        }
    }
}

// ============================================================
// Fused attention: per (bh, q-tile of 128) block.
// Streams causal K tiles: S = QK^T/32 (k=1024), online softmax, O += P·V.
// ============================================================
struct AttnSmem {
    float As[8][128];
    float Bs[8][128];
    float Pt[128][129];   // transposed P: Pt[k][row]
    float Vs[128][68];    // V tile, padded
    float m_s[128];
    float l_s[128];
    float alpha_s[128];
    float red[128][16];
};
#define ATTN_SMEM_BYTES (sizeof(AttnSmem))

__global__ __launch_bounds__(256) void k_attn() {
    extern __shared__ char smem_raw[];
    AttnSmem& S = *reinterpret_cast<AttnSmem*>(smem_raw);

    const int bh = blockIdx.y;
    const int qb = blockIdx.x;
    const int n0 = qb * 128;
    const float* __restrict__ Qp = g_Q + (size_t)bh * Nc * Dc;
    const float* __restrict__ Kp = g_K + (size_t)bh * Nc * Dc;
    const float* __restrict__ Vp = g_V + (size_t)bh * Nc * DHc;

    const int tid = threadIdx.x;
    const int colgrp = tid & 15;
    const int tm = (tid >> 4) << 3;   // 8 S-rows / O-rows
    const int tn = colgrp << 3;       // 8 S-cols
    const int tc = colgrp << 2;       // 4 O-cols (V dim)
    const int ar = tid >> 1, ac = (tid & 1) << 2;

    // init state
    if (tid < 128) { S.m_s[tid] = -1e30f; S.l_s[tid] = 0.f; }
    float O[8][4];
#pragma unroll
    for (int i = 0; i < 8; i++)
#pragma unroll
        for (int c = 0; c < 4; c++) O[i][c] = 0.f;

    for (int kb = 0; kb <= qb; kb++) {
        const int m0 = kb * 128;

        // ---- phase a: S = Q K^T over k=1024 ----
        float acc[8][8];
#pragma unroll
        for (int i = 0; i < 8; i++)
#pragma unroll
            for (int j = 0; j < 8; j++) acc[i][j] = 0.f;

        for (int k0 = 0; k0 < Dc; k0 += 8) {
            float4 av = *(const float4*)(Qp + (size_t)(n0 + ar) * Dc + k0 + ac);
            float4 bv = *(const float4*)(Kp + (size_t)(m0 + ar) * Dc + k0 + ac);
            __syncthreads();   // also protects Pt/Vs/red from previous phases
            S.As[ac + 0][ar] = av.x; S.As[ac + 1][ar] = av.y;
            S.As[ac + 2][ar] = av.z; S.As[ac + 3][ar] = av.w;
            S.Bs[ac + 0][ar] = bv.x; S.Bs[ac + 1][ar] = bv.y;
            S.Bs[ac + 2][ar] = bv.z; S.Bs[ac + 3][ar] = bv.w;
            __syncthreads();
#pragma unroll
            for (int k = 0; k < 8; k++) {
                float a[8], b[8];
                *(float4*)&a[0] = *(const float4*)&S.As[k][tm];
                *(float4*)&a[4] = *(const float4*)&S.As[k][tm + 4];
                *(float4*)&b[0] = *(const float4*)&S.Bs[k][tn];
                *(float4*)&b[4] = *(const float4*)&S.Bs[k][tn + 4];
#pragma unroll
                for (int i = 0; i < 8; i++)
#pragma unroll
                    for (int j = 0; j < 8; j++) acc[i][j] += a[i] * b[j];
            }
        }

        // ---- phase b: scale + causal mask + partial row max ----
        const float scale = 0.03125f;  // 1/sqrt(1024)
#pragma unroll
        for (int i = 0; i < 8; i++)
#pragma unroll
            for (int j = 0; j < 8; j++) acc[i][j] *= scale;
        if (kb == qb) {
#pragma unroll
            for (int i = 0; i < 8; i++)
#pragma unroll
                for (int j = 0; j < 8; j++)
                    if (tn + j > tm + i) acc[i][j] = -1e30f;
        }
#pragma unroll
        for (int i = 0; i < 8; i++) {
            float pm = acc[i][0];
#pragma unroll
            for (int j = 1; j < 8; j++) pm = fmaxf(pm, acc[i][j]);
            S.red[tm + i][colgrp] = pm;
        }
        __syncthreads();

        // ---- phase c: finalize row max, alpha, rescale l ----
        if (tid < 128) {
            float mo = S.m_s[tid];
            float mx = mo;
#pragma unroll
            for (int g = 0; g < 16; g++) mx = fmaxf(mx, S.red[tid][g]);
            float al = __expf(mo - mx);
            S.m_s[tid] = mx;
            S.alpha_s[tid] = al;
            S.l_s[tid] *= al;
        }
        __syncthreads();

        // ---- phase d: P = exp(S-m), write Pt, partial sums, rescale O, load V ----
        float mrow[8];
#pragma unroll
        for (int i = 0; i < 8; i++) mrow[i] = S.m_s[tm + i];
        float psum[8];
#pragma unroll
        for (int i = 0; i < 8; i++) {
            psum[i] = 0.f;
#pragma unroll
            for (int j = 0; j < 8; j++) {
                float p = __expf(acc[i][j] - mrow[i]);
                S.Pt[tn + j][tm + i] = p;
                psum[i] += p;
            }
            S.red[tm + i][colgrp] = psum[i];
        }
#pragma unroll
        for (int i = 0; i < 8; i++) {
            float al = S.alpha_s[tm + i];
#pragma unroll
            for (int c = 0; c < 4; c++) O[i][c] *= al;
        }
        // V tile load: 128x64 floats, 8 float4 per thread
#pragma unroll
        for (int r = 0; r < 8; r++) {
            int idx = tid + r * 256;         // float4 index
            int vrow = idx >> 4, vc4 = (idx & 15) << 2;
            float4 vv = *(const float4*)(Vp + (size_t)(m0 + vrow) * DHc + vc4);
            *(float4*)&S.Vs[vrow][vc4] = vv;
        }
        __syncthreads();

        // ---- phase e: finalize row sums ----
        if (tid < 128) {
            float s = 0.f;
#pragma unroll
            for (int g = 0; g < 16; g++) s += S.red[tid][g];
            S.l_s[tid] += s;
        }

        // ---- phase f: O += P · V ----
#pragma unroll 4
        for (int k = 0; k < 128; k++) {
            float a8[8];
#pragma unroll
            for (int i = 0; i < 8; i++) a8[i] = S.Pt[k][tm + i];
            float b4[4];
#pragma unroll
            for (int c = 0; c < 4; c++) b4[c] = S.Vs[k][tc + c];
#pragma unroll
            for (int i = 0; i < 8; i++)
#pragma unroll
                for (int c = 0; c < 4; c++) O[i][c] += a8[i] * b4[c];
        }
    }

    __syncthreads();
    const int b_ = bh >> 4, h = bh & 15;
#pragma unroll
    for (int i = 0; i < 8; i++) {
        const int n = n0 + tm + i;
        const float inv = 1.f / S.l_s[tm + i];
#pragma unroll
        for (int c = 0; c < 4; c++)
            g_SA[((size_t)(b_ * Nc + n)) * Dc + h * DHc + tc + c] = O[i][c] * inv;
    }
}

// ============================================================
// GEMM4: out = SA(4096x1024) @ Wp(1024x1024) + bp
// ============================================================
__global__ __launch_bounds__(256) void k_proj(const float* __restrict__ Wp,
                                              const float* __restrict__ bp,
                                              float* __restrict__ out) {
    const int m0 = blockIdx.x * 128;
    const int e0 = blockIdx.y * 128;

    __shared__ float As[8][128];
    __shared__ float Bs[8][128];

    const int tid = threadIdx.x;
    const int tm = (tid >> 4) << 3;
    const int tn = (tid & 15) << 3;
    const int ar = tid >> 1, ac = (tid & 1) << 2;
    const int br = tid >> 5, bc = (tid & 31) << 2;

    float acc[8][8];
#pragma unroll
    for (int i = 0; i < 8; i++)
#pragma unroll
        for (int j = 0; j < 8; j++) acc[i][j] = 0.f;

    for (int k0 = 0; k0 < Dc; k0 += 8) {
        float4 av = *(const float4*)(g_SA + (size_t)(m0 + ar) * Dc + k0 + ac);
        float4 bv = *(const float4*)(Wp + (size_t)(k0 + br) * Dc + e0 + bc);
        __syncthreads();
        As[ac + 0][ar] = av.x; As[ac + 1][ar] = av.y;
        As[ac + 2][ar] = av.z; As[ac + 3][ar] = av.w;
        Bs[br][bc + 0] = bv.x; Bs[br][bc + 1] = bv.y;
        Bs[br][bc + 2] = bv.z; Bs[br][bc + 3] = bv.w;
        __syncthreads();
#pragma unroll
        for (int k = 0; k < 8; k++) {
            float a[8], b[8];
            *(float4*)&a[0] = *(const float4*)&As[k][tm];
            *(float4*)&a[4] = *(const float4*)&As[k][tm + 4];
            *(float4*)&b[0] = *(const float4*)&Bs[k][tn];
            *(float4*)&b[4] = *(const float4*)&Bs[k][tn + 4];
#pragma unroll
            for (int i = 0; i < 8; i++)
#pragma unroll
                for (int j = 0; j < 8; j++) acc[i][j] += a[i] * b[j];
        }
    }

#pragma unroll
    for (int i = 0; i < 8; i++) {
        const int m = m0 + tm + i;
#pragma unroll
        for (int j = 0; j < 8; j++) {
            const int e = e0 + tn + j;
            out[(size_t)m * Dc + e] = acc[i][j] + bp[e];
        }
    }
}

// ============================================================
extern "C" void kernel_launch(void* const* d_in, const int* in_sizes, int n_in,
                              void* d_out, int out_size) {
    const float* x    = (const float*)d_in[0];
    const float* Wkqv = (const float*)d_in[1];
    const float* bkqv = (const float*)d_in[2];
    const float* Wp   = (const float*)d_in[3];
    const float* bp   = (const float*)d_in[4];
    float* out = (float*)d_out;

    cudaFuncSetAttribute(k_attn, cudaFuncAttributeMaxDynamicSharedMemorySize,
                         (int)ATTN_SMEM_BYTES);

    k_qkv<<<dim3(Mc / 128, (Ec + 127) / 128, Hc), 256>>>(x, Wkqv, bkqv);
    k_attn<<<dim3(Nc / 128, Bc * Hc), 256, ATTN_SMEM_BYTES>>>();
    k_proj<<<dim3(Mc / 128, Dc / 128), 256>>>(Wp, bp, out);
}

// round 5
// speedup vs baseline: 2.0207x; 2.0207x over previous
#include <cuda_runtime.h>
#include <cuda_bf16.h>
#include <math.h>
#include <stdint.h>

// CausalSelfAttention: B=4, N=1024, D=1024, H=16, DH=64
// Round-5: resubmit of round-4 (container infra flake, kernel never measured).
// bf16-split (hi+lo, 3-term) tensor-core GEMMs via mma.sync.m16n8k16.
//   error ~2^-16 per product => fp32-class accuracy, ~1.16 TF executed HMMA.

#define Bc 4
#define Nc 1024
#define Dc 1024
#define Hc 16
#define DHc 64
#define Ec (2 * Dc + DHc)   // 2112
#define Mc (Bc * Nc)        // 4096

// ---- scratch ----
__device__ float g_Q[(size_t)Bc * Hc * Nc * Dc];   // [bh, n, d]
__device__ float g_K[(size_t)Bc * Hc * Nc * Dc];
__device__ float g_V[(size_t)Bc * Hc * Nc * DHc];
__device__ float g_SA[(size_t)Bc * Nc * Dc];       // [b, n, h*DH+dh]

// ---- mma.sync m16n8k16 row.col f32.bf16.bf16.f32 ----
__device__ __forceinline__ void mma_bf16(float* d, const uint32_t* a, const uint32_t* b) {
    asm volatile(
        "mma.sync.aligned.m16n8k16.row.col.f32.bf16.bf16.f32 "
        "{%0,%1,%2,%3}, {%4,%5,%6,%7}, {%8,%9}, {%0,%1,%2,%3};"
        : "+f"(d[0]), "+f"(d[1]), "+f"(d[2]), "+f"(d[3])
        : "r"(a[0]), "r"(a[1]), "r"(a[2]), "r"(a[3]), "r"(b[0]), "r"(b[1]));
}

// split two floats into (hi bf16x2, lo bf16x2)
__device__ __forceinline__ void split2(float x, float y, __nv_bfloat162& hi, __nv_bfloat162& lo) {
    hi = __floats2bfloat162_rn(x, y);
    lo = __floats2bfloat162_rn(x - __bfloat162float(hi.x), y - __bfloat162float(hi.y));
}

// Fragment load + 48 MMAs for one k16 step over a 128x128 CTA tile.
// A tiles: [128 rows][24] bf16 (row-major, k-contig). B tiles: [128 n][24] bf16 (k-contig).
// Thread mapping per PTX m16n8k16: r = t>>2, c2 = (t&3)*2. Warp tile 64x32,
// warp grid 2(M) x 4(N): wm = (w>>2)*64, wn = (w&3)*32.
#define MMA_STEP(AHI, ALO, BHI, BLO, ACC)                                        \
    {                                                                             \
        uint32_t ah[4][4], al[4][4], bh[4][2], bl[4][2];                          \
        _Pragma("unroll")                                                         \
        for (int mi = 0; mi < 4; mi++) {                                          \
            const int r0 = wm + mi * 16 + r;                                      \
            ah[mi][0] = *(const uint32_t*)&AHI[r0][c2];                           \
            ah[mi][1] = *(const uint32_t*)&AHI[r0 + 8][c2];                       \
            ah[mi][2] = *(const uint32_t*)&AHI[r0][c2 + 8];                       \
            ah[mi][3] = *(const uint32_t*)&AHI[r0 + 8][c2 + 8];                   \
            al[mi][0] = *(const uint32_t*)&ALO[r0][c2];                           \
            al[mi][1] = *(const uint32_t*)&ALO[r0 + 8][c2];                       \
            al[mi][2] = *(const uint32_t*)&ALO[r0][c2 + 8];                       \
            al[mi][3] = *(const uint32_t*)&ALO[r0 + 8][c2 + 8];                   \
        }                                                                         \
        _Pragma("unroll")                                                         \
        for (int ni = 0; ni < 4; ni++) {                                          \
            const int nn = wn + ni * 8 + r;                                       \
            bh[ni][0] = *(const uint32_t*)&BHI[nn][c2];                           \
            bh[ni][1] = *(const uint32_t*)&BHI[nn][c2 + 8];                       \
            bl[ni][0] = *(const uint32_t*)&BLO[nn][c2];                           \
            bl[ni][1] = *(const uint32_t*)&BLO[nn][c2 + 8];                       \
        }                                                                         \
        _Pragma("unroll")                                                         \
        for (int mi = 0; mi < 4; mi++)                                            \
            _Pragma("unroll")                                                     \
            for (int ni = 0; ni < 4; ni++) {                                      \
                mma_bf16(ACC[mi][ni], ah[mi], bh[ni]);                            \
                mma_bf16(ACC[mi][ni], ah[mi], bl[ni]);                            \
                mma_bf16(ACC[mi][ni], al[mi], bh[ni]);                            \
            }                                                                     \
    }

// ============================================================
// GEMM1: QKV projection (tensor core). X(4096x1024) @ Wkqv[h](1024x2112)+bias.
// ============================================================
__global__ __launch_bounds__(256) void k_qkv(const float* __restrict__ x,
                                             const float* __restrict__ W,
                                             const float* __restrict__ bias) {
    const int h  = blockIdx.z;
    const int m0 = blockIdx.x * 128;
    const int e0 = blockIdx.y * 128;
    const float* __restrict__ Wh = W + (size_t)h * Dc * Ec;

    __shared__ __nv_bfloat16 Ahi[128][24], Alo[128][24], Bhi[128][24], Blo[128][24];

    const int tid = threadIdx.x;
    const int w = tid >> 5, t = tid & 31;
    const int wm = (w >> 2) * 64, wn = (w & 3) * 32;
    const int r = t >> 2, c2 = (t & 3) * 2;

    // staging assignments
    const int a_row = tid >> 1, a_k = (tid & 1) * 8;          // A: 2 float4 along k
    const int b_k2 = (tid & 7) * 2, b_e = (tid >> 3) * 4;     // B: 2 rows x 4 cols
    const bool b_ok = (e0 + b_e) < Ec;

    float acc[4][4][4];
#pragma unroll
    for (int mi = 0; mi < 4; mi++)
#pragma unroll
        for (int ni = 0; ni < 4; ni++)
#pragma unroll
            for (int q = 0; q < 4; q++) acc[mi][ni][q] = 0.f;

    for (int k0 = 0; k0 < Dc; k0 += 16) {
        float4 av0 = *(const float4*)(x + (size_t)(m0 + a_row) * Dc + k0 + a_k);
        float4 av1 = *(const float4*)(x + (size_t)(m0 + a_row) * Dc + k0 + a_k + 4);
        float4 bv0 = make_float4(0.f, 0.f, 0.f, 0.f), bv1 = bv0;
        if (b_ok) {
            bv0 = *(const float4*)(Wh + (size_t)(k0 + b_k2) * Ec + e0 + b_e);
            bv1 = *(const float4*)(Wh + (size_t)(k0 + b_k2 + 1) * Ec + e0 + b_e);
        }
        __syncthreads();
        // A: pack k-adjacent pairs
        {
            __nv_bfloat162 h2, l2;
            split2(av0.x, av0.y, h2, l2);
            *(__nv_bfloat162*)&Ahi[a_row][a_k + 0] = h2; *(__nv_bfloat162*)&Alo[a_row][a_k + 0] = l2;
            split2(av0.z, av0.w, h2, l2);
            *(__nv_bfloat162*)&Ahi[a_row][a_k + 2] = h2; *(__nv_bfloat162*)&Alo[a_row][a_k + 2] = l2;
            split2(av1.x, av1.y, h2, l2);
            *(__nv_bfloat162*)&Ahi[a_row][a_k + 4] = h2; *(__nv_bfloat162*)&Alo[a_row][a_k + 4] = l2;
            split2(av1.z, av1.w, h2, l2);
            *(__nv_bfloat162*)&Ahi[a_row][a_k + 6] = h2; *(__nv_bfloat162*)&Alo[a_row][a_k + 6] = l2;
        }
        // B transpose-stage: pack (k, k+1) pairs per n column
        {
            const float w0[4] = {bv0.x, bv0.y, bv0.z, bv0.w};
            const float w1[4] = {bv1.x, bv1.y, bv1.z, bv1.w};
#pragma unroll
            for (int j = 0; j < 4; j++) {
                __nv_bfloat162 h2, l2;
                split2(w0[j], w1[j], h2, l2);
                *(__nv_bfloat162*)&Bhi[b_e + j][b_k2] = h2;
                *(__nv_bfloat162*)&Blo[b_e + j][b_k2] = l2;
            }
        }
        __syncthreads();
        MMA_STEP(Ahi, Alo, Bhi, Blo, acc)
    }

    // epilogue: route to K / Q / V with bias
#pragma unroll
    for (int mi = 0; mi < 4; mi++) {
#pragma unroll
        for (int s = 0; s < 2; s++) {
            const int mm = m0 + wm + mi * 16 + r + s * 8;
            const int b_ = mm >> 10;
            const int n  = mm & (Nc - 1);
            const size_t base = (size_t)(b_ * Hc + h) * Nc + n;
#pragma unroll
            for (int ni = 0; ni < 4; ni++) {
#pragma unroll
                for (int cc = 0; cc < 2; cc++) {
                    const int e = e0 + wn + ni * 8 + c2 + cc;
                    if (e < Ec) {
                        const float v = acc[mi][ni][s * 2 + cc] + bias[h * Ec + e];
                        if (e < Dc)            g_K[base * Dc + e] = v;
                        else if (e < 2 * Dc)   g_Q[base * Dc + (e - Dc)] = v;
                        else                   g_V[base * DHc + (e - 2 * Dc)] = v;
                    }
                }
            }
        }
    }
}

// ============================================================
// Fused attention, S-GEMM on tensor cores.
// ============================================================
struct AttnSmem {
    __nv_bfloat16 Ahi[128][24], Alo[128][24], Bhi[128][24], Blo[128][24];
    float Pt[128][129];   // transposed P: Pt[col][row]
    float Vs[128][68];
    float m_s[128], l_s[128], alpha_s[128];
    float red[128][16];
};
#define ATTN_SMEM_BYTES (sizeof(AttnSmem))

__global__ __launch_bounds__(256) void k_attn() {
    extern __shared__ char smem_raw[];
    AttnSmem& S = *reinterpret_cast<AttnSmem*>(smem_raw);

    const int bh = blockIdx.y;
    const int qb = blockIdx.x;
    const int n0 = qb * 128;
    const float* __restrict__ Qp = g_Q + (size_t)bh * Nc * Dc;
    const float* __restrict__ Kp = g_K + (size_t)bh * Nc * Dc;
    const float* __restrict__ Vp = g_V + (size_t)bh * Nc * DHc;

    const int tid = threadIdx.x;
    const int w = tid >> 5, t = tid & 31;
    const int wm = (w >> 2) * 64, wn = (w & 3) * 32;
    const int r = t >> 2, c2 = (t & 3) * 2;
    const int slot = (w & 3) * 4 + (t & 3);   // 0..15: per-row partial slot / V col group
    const int tc = slot * 4;                  // 4 V columns

    const int a_row = tid >> 1, a_k = (tid & 1) * 8;

    if (tid < 128) { S.m_s[tid] = -1e30f; S.l_s[tid] = 0.f; }

    float O[8][4];   // rows: or = mi*2+s -> wm+mi*16+r+s*8
#pragma unroll
    for (int i = 0; i < 8; i++)
#pragma unroll
        for (int c = 0; c < 4; c++) O[i][c] = 0.f;

    for (int kb = 0; kb <= qb; kb++) {
        const int m0 = kb * 128;

        // ---- S = Q K^T (k=1024, bf16-split tensor core) ----
        float acc[4][4][4];
#pragma unroll
        for (int mi = 0; mi < 4; mi++)
#pragma unroll
            for (int ni = 0; ni < 4; ni++)
#pragma unroll
                for (int q = 0; q < 4; q++) acc[mi][ni][q] = 0.f;

        for (int k0 = 0; k0 < Dc; k0 += 16) {
            float4 av0 = *(const float4*)(Qp + (size_t)(n0 + a_row) * Dc + k0 + a_k);
            float4 av1 = *(const float4*)(Qp + (size_t)(n0 + a_row) * Dc + k0 + a_k + 4);
            float4 bv0 = *(const float4*)(Kp + (size_t)(m0 + a_row) * Dc + k0 + a_k);
            float4 bv1 = *(const float4*)(Kp + (size_t)(m0 + a_row) * Dc + k0 + a_k + 4);
            __syncthreads();   // also fences Pt/Vs/red reads from previous phases
            __nv_bfloat162 h2, l2;
            split2(av0.x, av0.y, h2, l2);
            *(__nv_bfloat162*)&S.Ahi[a_row][a_k + 0] = h2; *(__nv_bfloat162*)&S.Alo[a_row][a_k + 0] = l2;
            split2(av0.z, av0.w, h2, l2);
            *(__nv_bfloat162*)&S.Ahi[a_row][a_k + 2] = h2; *(__nv_bfloat162*)&S.Alo[a_row][a_k + 2] = l2;
            split2(av1.x, av1.y, h2, l2);
            *(__nv_bfloat162*)&S.Ahi[a_row][a_k + 4] = h2; *(__nv_bfloat162*)&S.Alo[a_row][a_k + 4] = l2;
            split2(av1.z, av1.w, h2, l2);
            *(__nv_bfloat162*)&S.Ahi[a_row][a_k + 6] = h2; *(__nv_bfloat162*)&S.Alo[a_row][a_k + 6] = l2;
            split2(bv0.x, bv0.y, h2, l2);
            *(__nv_bfloat162*)&S.Bhi[a_row][a_k + 0] = h2; *(__nv_bfloat162*)&S.Blo[a_row][a_k + 0] = l2;
            split2(bv0.z, bv0.w, h2, l2);
            *(__nv_bfloat162*)&S.Bhi[a_row][a_k + 2] = h2; *(__nv_bfloat162*)&S.Blo[a_row][a_k + 2] = l2;
            split2(bv1.x, bv1.y, h2, l2);
            *(__nv_bfloat162*)&S.Bhi[a_row][a_k + 4] = h2; *(__nv_bfloat162*)&S.Blo[a_row][a_k + 4] = l2;
            split2(bv1.z, bv1.w, h2, l2);
            *(__nv_bfloat162*)&S.Bhi[a_row][a_k + 6] = h2; *(__nv_bfloat162*)&S.Blo[a_row][a_k + 6] = l2;
            __syncthreads();
            MMA_STEP(S.Ahi, S.Alo, S.Bhi, S.Blo, acc)
        }

        // ---- scale + causal mask + partial row max ----
        const float scale = 0.03125f;
#pragma unroll
        for (int mi = 0; mi < 4; mi++)
#pragma unroll
            for (int ni = 0; ni < 4; ni++)
#pragma unroll
                for (int q = 0; q < 4; q++) acc[mi][ni][q] *= scale;
        if (kb == qb) {
#pragma unroll
            for (int mi = 0; mi < 4; mi++)
#pragma unroll
                for (int ni = 0; ni < 4; ni++)
#pragma unroll
                    for (int q = 0; q < 4; q++) {
                        const int rr = wm + mi * 16 + r + (q >> 1) * 8;
                        const int nn = wn + ni * 8 + c2 + (q & 1);
                        if (nn > rr) acc[mi][ni][q] = -1e30f;
                    }
        }
#pragma unroll
        for (int mi = 0; mi < 4; mi++)
#pragma unroll
            for (int s = 0; s < 2; s++) {
                float pm = -1e30f;
#pragma unroll
                for (int ni = 0; ni < 4; ni++) {
                    pm = fmaxf(pm, acc[mi][ni][s * 2]);
                    pm = fmaxf(pm, acc[mi][ni][s * 2 + 1]);
                }
                S.red[wm + mi * 16 + r + s * 8][slot] = pm;
            }
        __syncthreads();

        // ---- finalize row max, alpha, rescale l ----
        if (tid < 128) {
            const float mo = S.m_s[tid];
            float mx = mo;
#pragma unroll
            for (int g = 0; g < 16; g++) mx = fmaxf(mx, S.red[tid][g]);
            const float al = __expf(mo - mx);
            S.m_s[tid] = mx;
            S.alpha_s[tid] = al;
            S.l_s[tid] *= al;
        }
        __syncthreads();

        // ---- P = exp(S-m) -> Pt, partial sums, rescale O, load V ----
#pragma unroll
        for (int mi = 0; mi < 4; mi++) {
#pragma unroll
            for (int s = 0; s < 2; s++) {
                const int rowg = wm + mi * 16 + r + s * 8;
                const float mrow = S.m_s[rowg];
                float ps = 0.f;
#pragma unroll
                for (int ni = 0; ni < 4; ni++) {
                    const int nn = wn + ni * 8 + c2;
                    const float p0 = __expf(acc[mi][ni][s * 2 + 0] - mrow);
                    const float p1 = __expf(acc[mi][ni][s * 2 + 1] - mrow);
                    S.Pt[nn][rowg] = p0;
                    S.Pt[nn + 1][rowg] = p1;
                    ps += p0 + p1;
                }
                S.red[rowg][slot] = ps;
                const float al = S.alpha_s[rowg];
#pragma unroll
                for (int c = 0; c < 4; c++) O[mi * 2 + s][c] *= al;
            }
        }
#pragma unroll
        for (int rep = 0; rep < 8; rep++) {
            const int idx = tid + rep * 256;          // float4 index over 128x64
            const int vrow = idx >> 4, vc4 = (idx & 15) << 2;
            float4 vv = *(const float4*)(Vp + (size_t)(m0 + vrow) * DHc + vc4);
            *(float4*)&S.Vs[vrow][vc4] = vv;
        }
        __syncthreads();

        // ---- finalize row sums ----
        if (tid < 128) {
            float sm = 0.f;
#pragma unroll
            for (int g = 0; g < 16; g++) sm += S.red[tid][g];
            S.l_s[tid] += sm;
        }

        // ---- O += P V (fp32 FFMA; reads Pt, Vs written before sync) ----
        int rows[8];
#pragma unroll
        for (int mi = 0; mi < 4; mi++) {
            rows[mi * 2 + 0] = wm + mi * 16 + r;
            rows[mi * 2 + 1] = wm + mi * 16 + r + 8;
        }
#pragma unroll 4
        for (int k = 0; k < 128; k++) {
            float a8[8];
#pragma unroll
            for (int i = 0; i < 8; i++) a8[i] = S.Pt[k][rows[i]];
            float4 bv = *(const float4*)&S.Vs[k][tc];
            const float b4[4] = {bv.x, bv.y, bv.z, bv.w};
#pragma unroll
            for (int i = 0; i < 8; i++)
#pragma unroll
                for (int c = 0; c < 4; c++) O[i][c] += a8[i] * b4[c];
        }
    }

    __syncthreads();
    const int b_ = bh >> 4, h = bh & 15;
#pragma unroll
    for (int mi = 0; mi < 4; mi++)
#pragma unroll
        for (int s = 0; s < 2; s++) {
            const int rowg = wm + mi * 16 + r + s * 8;
            const int n = n0 + rowg;
            const float inv = 1.f / S.l_s[rowg];
#pragma unroll
            for (int c = 0; c < 4; c++)
                g_SA[((size_t)(b_ * Nc + n)) * Dc + h * DHc + tc + c] = O[mi * 2 + s][c] * inv;
        }
}

// ============================================================
// GEMM4: out = SA(4096x1024) @ Wp(1024x1024) + bp  (tensor core)
// ============================================================
__global__ __launch_bounds__(256) void k_proj(const float* __restrict__ Wp,
                                              const float* __restrict__ bp,
                                              float* __restrict__ out) {
    const int m0 = blockIdx.x * 128;
    const int e0 = blockIdx.y * 128;

    __shared__ __nv_bfloat16 Ahi[128][24], Alo[128][24], Bhi[128][24], Blo[128][24];

    const int tid = threadIdx.x;
    const int w = tid >> 5, t = tid & 31;
    const int wm = (w >> 2) * 64, wn = (w & 3) * 32;
    const int r = t >> 2, c2 = (t & 3) * 2;

    const int a_row = tid >> 1, a_k = (tid & 1) * 8;
    const int b_k2 = (tid & 7) * 2, b_e = (tid >> 3) * 4;

    float acc[4][4][4];
#pragma unroll
    for (int mi = 0; mi < 4; mi++)
#pragma unroll
        for (int ni = 0; ni < 4; ni++)
#pragma unroll
            for (int q = 0; q < 4; q++) acc[mi][ni][q] = 0.f;

    for (int k0 = 0; k0 < Dc; k0 += 16) {
        float4 av0 = *(const float4*)(g_SA + (size_t)(m0 + a_row) * Dc + k0 + a_k);
        float4 av1 = *(const float4*)(g_SA + (size_t)(m0 + a_row) * Dc + k0 + a_k + 4);
        float4 bv0 = *(const float4*)(Wp + (size_t)(k0 + b_k2) * Dc + e0 + b_e);
        float4 bv1 = *(const float4*)(Wp + (size_t)(k0 + b_k2 + 1) * Dc + e0 + b_e);
        __syncthreads();
        __nv_bfloat162 h2, l2;
        split2(av0.x, av0.y, h2, l2);
        *(__nv_bfloat162*)&Ahi[a_row][a_k + 0] = h2; *(__nv_bfloat162*)&Alo[a_row][a_k + 0] = l2;
        split2(av0.z, av0.w, h2, l2);
        *(__nv_bfloat162*)&Ahi[a_row][a_k + 2] = h2; *(__nv_bfloat162*)&Alo[a_row][a_k + 2] = l2;
        split2(av1.x, av1.y, h2, l2);
        *(__nv_bfloat162*)&Ahi[a_row][a_k + 4] = h2; *(__nv_bfloat162*)&Alo[a_row][a_k + 4] = l2;
        split2(av1.z, av1.w, h2, l2);
        *(__nv_bfloat162*)&Ahi[a_row][a_k + 6] = h2; *(__nv_bfloat162*)&Alo[a_row][a_k + 6] = l2;
        {
            const float w0[4] = {bv0.x, bv0.y, bv0.z, bv0.w};
            const float w1[4] = {bv1.x, bv1.y, bv1.z, bv1.w};
#pragma unroll
            for (int j = 0; j < 4; j++) {
                split2(w0[j], w1[j], h2, l2);
                *(__nv_bfloat162*)&Bhi[b_e + j][b_k2] = h2;
                *(__nv_bfloat162*)&Blo[b_e + j][b_k2] = l2;
            }
        }
        __syncthreads();
        MMA_STEP(Ahi, Alo, Bhi, Blo, acc)
    }

#pragma unroll
    for (int mi = 0; mi < 4; mi++)
#pragma unroll
        for (int s = 0; s < 2; s++) {
            const int m = m0 + wm + mi * 16 + r + s * 8;
#pragma unroll
            for (int ni = 0; ni < 4; ni++)
#pragma unroll
                for (int cc = 0; cc < 2; cc++) {
                    const int e = e0 + wn + ni * 8 + c2 + cc;
                    out[(size_t)m * Dc + e] = acc[mi][ni][s * 2 + cc] + bp[e];
                }
        }
}

// ============================================================
extern "C" void kernel_launch(void* const* d_in, const int* in_sizes, int n_in,
                              void* d_out, int out_size) {
    const float* x    = (const float*)d_in[0];
    const float* Wkqv = (const float*)d_in[1];
    const float* bkqv = (const float*)d_in[2];
    const float* Wp   = (const float*)d_in[3];
    const float* bp   = (const float*)d_in[4];
    float* out = (float*)d_out;

    cudaFuncSetAttribute(k_attn, cudaFuncAttributeMaxDynamicSharedMemorySize,
                         (int)ATTN_SMEM_BYTES);

    k_qkv<<<dim3(Mc / 128, (Ec + 127) / 128, Hc), 256>>>(x, Wkqv, bkqv);
    k_attn<<<dim3(Nc / 128, Bc * Hc), 256, ATTN_SMEM_BYTES>>>();
    k_proj<<<dim3(Mc / 128, Dc / 128), 256>>>(Wp, bp, out);
}